// round 2
// baseline (speedup 1.0000x reference)
#include <cuda_runtime.h>
#include <math_constants.h>

#define B_ROWS   4096
#define N_COL    16384
#define M_BINS   100
#define HSLOTS   101      // histogram slots 0..100
#define NTHREADS 256

// Dynamic smem: per-thread private histograms, layout [HSLOTS][NTHREADS].
// Thread t always accesses column t -> bank t%32 -> zero conflicts, zero atomics.
extern __shared__ float priv[];

__global__ __launch_bounds__(NTHREADS)
void roc_model_kernel(const float* __restrict__ x,
                      const float* __restrict__ y,
                      float* __restrict__ out)
{
    __shared__ float ts[104];          // exact t table + inf sentinels
    __shared__ float fhA[HSLOTS];      // partial reduction (cols 0..127)
    __shared__ float fhB[HSLOTS];      // partial reduction (cols 128..255)
    __shared__ float sfx[M_BINS];      // suffix sums

    const int row = blockIdx.x;
    const int tid = threadIdx.x;

    // zero private histogram column
    #pragma unroll
    for (int i = 0; i < HSLOTS; ++i) priv[i * NTHREADS + tid] = 0.0f;

    // Exact linspace(0,1,100) as JAX computes it: t[i] = fl(i / 99) (true division).
    if (tid < 100) ts[tid] = __fdiv_rn((float)tid, 99.0f);
    if (tid == 100 || tid == 101) ts[tid] = CUDART_INF_F;
    __syncthreads();

    // ---- Phase 1: value-sum histogram (no atomics, almost no table reads) ----
    const float4* xr = reinterpret_cast<const float4*>(x + (size_t)row * N_COL);

    #pragma unroll
    for (int it = 0; it < N_COL / 4 / NTHREADS; ++it) {
        float4 v = xr[tid + it * NTHREADS];
        float vv[4] = {v.x, v.y, v.z, v.w};
        #pragma unroll
        for (int c = 0; c < 4; ++c) {
            float xv = vv[c];
            float g  = xv * 99.0f;
            float r  = rintf(g);
            int i;
            if (__builtin_expect(fabsf(g - r) > 2e-4f, 1)) {
                // Far from any bin boundary: slot = ceil(99*x), exact.
                i = __float2int_ru(g);
            } else {
                // Rare (~0.04%): resolve against the exact boundary table.
                i = (int)g;
                if (i < 0) i = 0;
                if (i > 99) i = 99;
                while (ts[i] < xv) ++i;                 // ts[100]=inf terminates
                while (i > 0 && ts[i - 1] >= xv) --i;
            }
            priv[i * NTHREADS + tid] += xv;             // conflict-free LDS+FADD+STS
        }
    }
    __syncthreads();

    // ---- Phase 2: reduce 256 private columns (two halves in parallel) ----
    if (tid < HSLOTS) {
        const int base = tid * NTHREADS;
        float s0 = 0.f, s1 = 0.f, s2 = 0.f, s3 = 0.f;
        #pragma unroll 8
        for (int j = 0; j < 128; j += 4) {
            s0 += priv[base + ((j + 0 + tid) & 127)];
            s1 += priv[base + ((j + 1 + tid) & 127)];
            s2 += priv[base + ((j + 2 + tid) & 127)];
            s3 += priv[base + ((j + 3 + tid) & 127)];
        }
        fhA[tid] = (s0 + s1) + (s2 + s3);
    } else if (tid >= 128 && tid < 128 + HSLOTS) {
        const int b = tid - 128;
        const int base = b * NTHREADS + 128;
        float s0 = 0.f, s1 = 0.f, s2 = 0.f, s3 = 0.f;
        #pragma unroll 8
        for (int j = 0; j < 128; j += 4) {
            s0 += priv[base + ((j + 0 + b) & 127)];
            s1 += priv[base + ((j + 1 + b) & 127)];
            s2 += priv[base + ((j + 2 + b) & 127)];
            s3 += priv[base + ((j + 3 + b) & 127)];
        }
        fhB[b] = (s0 + s1) + (s2 + s3);
    }
    __syncthreads();
    if (tid < HSLOTS) fhA[tid] += fhB[tid];
    __syncthreads();

    // ---- Phase 3: suffix sums (serial on thread 0, matches flip-cumsum-flip order) ----
    if (tid == 0) {
        float acc = 0.0f;
        #pragma unroll
        for (int k = M_BINS - 1; k >= 0; --k) {
            float f = (k == M_BINS - 1) ? fhA[100] : fhA[k + 1];
            acc += f;
            sfx[k] = acc;
        }
    }
    __syncthreads();

    const float invy = 1.0f / y[row];

    // ---- Phase 4: write curves ----
    if (tid < M_BINS) {
        float roc = sfx[tid] * invy;
        out[(size_t)row * M_BINS + tid] = roc;

        float d;
        if (tid < M_BINS - 1) d = fhA[tid + 1] * invy;                   // bins[k]
        else                  d = (fhA[99] + fhA[98]) * 0.5f * invy;     // deriv_last
        out[(size_t)B_ROWS * M_BINS + (size_t)row * M_BINS + tid] = d;
    }

    // ---- Phase 5: trapz scalars (thread 0) ----
    if (tid == 0) {
        float t1 = 0.0f, t2 = 0.0f;
        float prev_r = sfx[0] * invy;
        float prev_d = fhA[1] * invy;
        #pragma unroll
        for (int k = 1; k < M_BINS; ++k) {
            float rr = sfx[k] * invy;
            float dd = (k < M_BINS - 1) ? fhA[k + 1] * invy
                                        : (fhA[99] + fhA[98]) * 0.5f * invy;
            t1 += (prev_r + rr) * 0.5f;
            t2 += (prev_d + dd) * 0.5f;
            prev_r = rr; prev_d = dd;
        }
        out[(size_t)B_ROWS * M_BINS * 2 + row]          = t1;
        out[(size_t)B_ROWS * M_BINS * 2 + B_ROWS + row] = t2;
    }
}

extern "C" void kernel_launch(void* const* d_in, const int* in_sizes, int n_in,
                              void* d_out, int out_size)
{
    const float* x = (const float*)d_in[0];   // [4096, 16384] fp32
    const float* y = (const float*)d_in[1];   // [4096] fp32
    float* out = (float*)d_out;

    const int smem = HSLOTS * NTHREADS * (int)sizeof(float);   // 103,424 B
    cudaFuncSetAttribute(roc_model_kernel,
                         cudaFuncAttributeMaxDynamicSharedMemorySize, smem);
    roc_model_kernel<<<B_ROWS, NTHREADS, smem>>>(x, y, out);
}

// round 4
// speedup vs baseline: 1.3959x; 1.3959x over previous
#include <cuda_runtime.h>
#include <math_constants.h>

#define B_ROWS   4096
#define N_COL    16384
#define M_BINS   100
#define HSLOTS   101      // histogram slots 0..100
#define NTHREADS 256
#define PF       8        // prefetch depth (float4 per stage)
#define NITER    (N_COL / 4 / NTHREADS)   // 16 float4 per thread
#define NSTAGE   (NITER / PF)             // 2 stages

// Dynamic smem: per-thread private histograms, layout [HSLOTS][NTHREADS].
// Thread t always accesses column t -> bank t%32 -> zero conflicts, zero atomics.
extern __shared__ float priv[];

__device__ __forceinline__ void bin_one(float xv, const float* __restrict__ ts, int tid)
{
    float g = xv * 99.0f;
    float r = rintf(g);
    int i;
    if (__builtin_expect(fabsf(g - r) > 2e-4f, 1)) {
        // Far from any bin boundary: slot = ceil(99*x), exact.
        i = __float2int_ru(g);
    } else {
        // Rare (~0.04%): resolve against the exact boundary table.
        i = (int)g;
        if (i < 0) i = 0;
        if (i > 99) i = 99;
        while (ts[i] < xv) ++i;                 // ts[100]=inf terminates
        while (i > 0 && ts[i - 1] >= xv) --i;
    }
    priv[i * NTHREADS + tid] += xv;             // conflict-free LDS+FADD+STS
}

__global__ __launch_bounds__(NTHREADS, 2)
void roc_model_kernel(const float* __restrict__ x,
                      const float* __restrict__ y,
                      float* __restrict__ out)
{
    __shared__ float ts[104];          // exact t table + inf sentinels
    __shared__ float fhA[HSLOTS];      // partial reduction (cols 0..127)
    __shared__ float fhB[HSLOTS];      // partial reduction (cols 128..255)
    __shared__ float sfx[M_BINS];      // suffix sums

    const int row = blockIdx.x;
    const int tid = threadIdx.x;

    const float4* xr = reinterpret_cast<const float4*>(x + (size_t)row * N_COL);

    // Kick off the first prefetch batch BEFORE anything else.
    float4 cur[PF], nxt[PF];
    #pragma unroll
    for (int j = 0; j < PF; ++j) cur[j] = xr[tid + j * NTHREADS];

    // zero private histogram column
    #pragma unroll
    for (int i = 0; i < HSLOTS; ++i) priv[i * NTHREADS + tid] = 0.0f;

    // Exact linspace(0,1,100) as JAX computes it: t[i] = fl(i / 99) (true division).
    if (tid < 100) ts[tid] = __fdiv_rn((float)tid, 99.0f);
    if (tid == 100 || tid == 101) ts[tid] = CUDART_INF_F;
    __syncthreads();

    // ---- Phase 1: software-pipelined histogram ----
    #pragma unroll
    for (int st = 0; st < NSTAGE; ++st) {
        if (st + 1 < NSTAGE) {
            #pragma unroll
            for (int j = 0; j < PF; ++j)
                nxt[j] = xr[tid + ((st + 1) * PF + j) * NTHREADS];
        }
        #pragma unroll
        for (int j = 0; j < PF; ++j) {
            bin_one(cur[j].x, ts, tid);
            bin_one(cur[j].y, ts, tid);
            bin_one(cur[j].z, ts, tid);
            bin_one(cur[j].w, ts, tid);
        }
        if (st + 1 < NSTAGE) {
            #pragma unroll
            for (int j = 0; j < PF; ++j) cur[j] = nxt[j];
        }
    }
    __syncthreads();

    // ---- Phase 2: reduce 256 private columns (two halves in parallel) ----
    if (tid < HSLOTS) {
        const int base = tid * NTHREADS;
        float s0 = 0.f, s1 = 0.f, s2 = 0.f, s3 = 0.f;
        #pragma unroll 8
        for (int j = 0; j < 128; j += 4) {
            s0 += priv[base + ((j + 0 + tid) & 127)];
            s1 += priv[base + ((j + 1 + tid) & 127)];
            s2 += priv[base + ((j + 2 + tid) & 127)];
            s3 += priv[base + ((j + 3 + tid) & 127)];
        }
        fhA[tid] = (s0 + s1) + (s2 + s3);
    } else if (tid >= 128 && tid < 128 + HSLOTS) {
        const int b = tid - 128;
        const int base = b * NTHREADS + 128;
        float s0 = 0.f, s1 = 0.f, s2 = 0.f, s3 = 0.f;
        #pragma unroll 8
        for (int j = 0; j < 128; j += 4) {
            s0 += priv[base + ((j + 0 + b) & 127)];
            s1 += priv[base + ((j + 1 + b) & 127)];
            s2 += priv[base + ((j + 2 + b) & 127)];
            s3 += priv[base + ((j + 3 + b) & 127)];
        }
        fhB[b] = (s0 + s1) + (s2 + s3);
    }
    __syncthreads();
    if (tid < HSLOTS) fhA[tid] += fhB[tid];
    __syncthreads();

    // ---- Phase 3: suffix sums (serial on thread 0, matches flip-cumsum-flip order) ----
    if (tid == 0) {
        float acc = 0.0f;
        #pragma unroll
        for (int k = M_BINS - 1; k >= 0; --k) {
            float f = (k == M_BINS - 1) ? fhA[100] : fhA[k + 1];
            acc += f;
            sfx[k] = acc;
        }
    }
    __syncthreads();

    const float invy = 1.0f / y[row];

    // ---- Phase 4: write curves ----
    if (tid < M_BINS) {
        float roc = sfx[tid] * invy;
        out[(size_t)row * M_BINS + tid] = roc;

        float d;
        if (tid < M_BINS - 1) d = fhA[tid + 1] * invy;                   // bins[k]
        else                  d = (fhA[99] + fhA[98]) * 0.5f * invy;     // deriv_last
        out[(size_t)B_ROWS * M_BINS + (size_t)row * M_BINS + tid] = d;
    }

    // ---- Phase 5: trapz scalars (thread 0) ----
    if (tid == 0) {
        float t1 = 0.0f, t2 = 0.0f;
        float prev_r = sfx[0] * invy;
        float prev_d = fhA[1] * invy;
        #pragma unroll
        for (int k = 1; k < M_BINS; ++k) {
            float rr = sfx[k] * invy;
            float dd = (k < M_BINS - 1) ? fhA[k + 1] * invy
                                        : (fhA[99] + fhA[98]) * 0.5f * invy;
            t1 += (prev_r + rr) * 0.5f;
            t2 += (prev_d + dd) * 0.5f;
            prev_r = rr; prev_d = dd;
        }
        out[(size_t)B_ROWS * M_BINS * 2 + row]          = t1;
        out[(size_t)B_ROWS * M_BINS * 2 + B_ROWS + row] = t2;
    }
}

extern "C" void kernel_launch(void* const* d_in, const int* in_sizes, int n_in,
                              void* d_out, int out_size)
{
    const float* x = (const float*)d_in[0];   // [4096, 16384] fp32
    const float* y = (const float*)d_in[1];   // [4096] fp32
    float* out = (float*)d_out;

    const int smem = HSLOTS * NTHREADS * (int)sizeof(float);   // 103,424 B
    cudaFuncSetAttribute(roc_model_kernel,
                         cudaFuncAttributeMaxDynamicSharedMemorySize, smem);
    roc_model_kernel<<<B_ROWS, NTHREADS, smem>>>(x, y, out);
}

// round 6
// speedup vs baseline: 1.4843x; 1.0634x over previous
#include <cuda_runtime.h>
#include <math_constants.h>

#define B_ROWS   4096
#define N_COL    16384
#define M_BINS   100
#define HSLOTS   101      // histogram slots 0..100
#define NTHREADS 256
#define NVEC     (N_COL / 4 / NTHREADS)   // 16 float4 per thread
#define EPS_NEAR 2e-4f

// Dynamic smem: per-thread private histograms, layout [HSLOTS][NTHREADS].
// Thread t always accesses column t -> bank t%32 -> zero conflicts, zero atomics.
extern __shared__ float priv[];

__global__ __launch_bounds__(NTHREADS, 2)
void roc_model_kernel(const float* __restrict__ x,
                      const float* __restrict__ y,
                      float* __restrict__ out)
{
    __shared__ float ts[104];          // exact t table + inf sentinels
    __shared__ float fhA[HSLOTS];      // partial reduction (cols 0..127)
    __shared__ float fhB[HSLOTS];      // partial reduction (cols 128..255)
    __shared__ float sfx[M_BINS];      // suffix sums

    const int row = blockIdx.x;
    const int tid = threadIdx.x;

    const float4* xr = reinterpret_cast<const float4*>(x + (size_t)row * N_COL);

    // Issue ALL row loads up front: 16 LDG.128 in flight per thread (max MLP).
    float4 v[NVEC];
    #pragma unroll
    for (int j = 0; j < NVEC; ++j) v[j] = xr[tid + j * NTHREADS];

    // zero private histogram column (overlaps load latency)
    #pragma unroll
    for (int i = 0; i < HSLOTS; ++i) priv[i * NTHREADS + tid] = 0.0f;

    // Exact linspace(0,1,100) as JAX computes it: t[i] = fl(i / 99) (true division).
    if (tid < 100) ts[tid] = __fdiv_rn((float)tid, 99.0f);
    if (tid == 100 || tid == 101) ts[tid] = CUDART_INF_F;
    __syncthreads();

    float* hp = priv + tid;            // this thread's column base

    // ---- Phase 1: branch-free binning, ballot-guarded rare fixup ----
    #pragma unroll
    for (int j = 0; j < NVEC; ++j) {
        float xv[4] = {v[j].x, v[j].y, v[j].z, v[j].w};
        int   idx[4];
        bool  near[4];
        bool  anynear = false;

        #pragma unroll
        for (int c = 0; c < 4; ++c) {
            float g = xv[c] * 99.0f;
            float r = rintf(g);
            near[c] = fabsf(g - r) <= EPS_NEAR;  // within ulp-band of a bin edge?
            anynear |= near[c];
            idx[c] = __float2int_ru(g);          // exact when not near a boundary
        }

        // Rare (~1.3% of quads warp-wide): resolve near-boundary elements
        // against the exact fl(i/99) table. Warp-uniform branch.
        if (__ballot_sync(0xffffffffu, anynear)) {
            #pragma unroll
            for (int c = 0; c < 4; ++c) {
                if (near[c]) {
                    float g = xv[c] * 99.0f;
                    int i = (int)g;
                    if (i < 0) i = 0;
                    if (i > 99) i = 99;
                    while (ts[i] < xv[c]) ++i;              // ts[100]=inf terminates
                    while (i > 0 && ts[i - 1] >= xv[c]) --i;
                    idx[c] = i;
                }
            }
        }

        #pragma unroll
        for (int c = 0; c < 4; ++c)
            hp[idx[c] * NTHREADS] += xv[c];      // conflict-free LDS+FADD+STS
    }
    __syncthreads();

    // ---- Phase 2: reduce 256 private columns (two halves in parallel) ----
    if (tid < HSLOTS) {
        const int base = tid * NTHREADS;
        float s0 = 0.f, s1 = 0.f, s2 = 0.f, s3 = 0.f;
        #pragma unroll 8
        for (int j = 0; j < 128; j += 4) {
            s0 += priv[base + ((j + 0 + tid) & 127)];
            s1 += priv[base + ((j + 1 + tid) & 127)];
            s2 += priv[base + ((j + 2 + tid) & 127)];
            s3 += priv[base + ((j + 3 + tid) & 127)];
        }
        fhA[tid] = (s0 + s1) + (s2 + s3);
    } else if (tid >= 128 && tid < 128 + HSLOTS) {
        const int b = tid - 128;
        const int base = b * NTHREADS + 128;
        float s0 = 0.f, s1 = 0.f, s2 = 0.f, s3 = 0.f;
        #pragma unroll 8
        for (int j = 0; j < 128; j += 4) {
            s0 += priv[base + ((j + 0 + b) & 127)];
            s1 += priv[base + ((j + 1 + b) & 127)];
            s2 += priv[base + ((j + 2 + b) & 127)];
            s3 += priv[base + ((j + 3 + b) & 127)];
        }
        fhB[b] = (s0 + s1) + (s2 + s3);
    }
    __syncthreads();
    if (tid < HSLOTS) fhA[tid] += fhB[tid];
    __syncthreads();

    // ---- Phase 3: suffix sums (serial on thread 0, matches flip-cumsum-flip order) ----
    if (tid == 0) {
        float acc = 0.0f;
        #pragma unroll
        for (int k = M_BINS - 1; k >= 0; --k) {
            float f = (k == M_BINS - 1) ? fhA[100] : fhA[k + 1];
            acc += f;
            sfx[k] = acc;
        }
    }
    __syncthreads();

    const float invy = 1.0f / y[row];

    // ---- Phase 4: write curves ----
    if (tid < M_BINS) {
        float roc = sfx[tid] * invy;
        out[(size_t)row * M_BINS + tid] = roc;

        float d;
        if (tid < M_BINS - 1) d = fhA[tid + 1] * invy;                   // bins[k]
        else                  d = (fhA[99] + fhA[98]) * 0.5f * invy;     // deriv_last
        out[(size_t)B_ROWS * M_BINS + (size_t)row * M_BINS + tid] = d;
    }

    // ---- Phase 5: trapz scalars (thread 0) ----
    if (tid == 0) {
        float t1 = 0.0f, t2 = 0.0f;
        float prev_r = sfx[0] * invy;
        float prev_d = fhA[1] * invy;
        #pragma unroll
        for (int k = 1; k < M_BINS; ++k) {
            float rr = sfx[k] * invy;
            float dd = (k < M_BINS - 1) ? fhA[k + 1] * invy
                                        : (fhA[99] + fhA[98]) * 0.5f * invy;
            t1 += (prev_r + rr) * 0.5f;
            t2 += (prev_d + dd) * 0.5f;
            prev_r = rr; prev_d = dd;
        }
        out[(size_t)B_ROWS * M_BINS * 2 + row]          = t1;
        out[(size_t)B_ROWS * M_BINS * 2 + B_ROWS + row] = t2;
    }
}

extern "C" void kernel_launch(void* const* d_in, const int* in_sizes, int n_in,
                              void* d_out, int out_size)
{
    const float* x = (const float*)d_in[0];   // [4096, 16384] fp32
    const float* y = (const float*)d_in[1];   // [4096] fp32
    float* out = (float*)d_out;

    const int smem = HSLOTS * NTHREADS * (int)sizeof(float);   // 103,424 B
    cudaFuncSetAttribute(roc_model_kernel,
                         cudaFuncAttributeMaxDynamicSharedMemorySize, smem);
    roc_model_kernel<<<B_ROWS, NTHREADS, smem>>>(x, y, out);
}